// round 14
// baseline (speedup 1.0000x reference)
#include <cuda_runtime.h>
#include <cuda_bf16.h>
#include <cstdint>

// ---- problem constants ----
#define T1n 128
#define T2n 512
#define TPn 8
#define Hn  16
#define Kn  4
#define Cn  129   // 2*K*H+1
#define Dn  256

// ---- device scratch ----
__device__ float  g_val[T1n * T2n];
__device__ uint2  g_pack[T1n * TPn * T2n];    // bucket-sorted compacted {awb, ap}
__device__ int    g_bs[T1n * TPn * 17];       // bucket starts (bs[16] = cnt)
__device__ float2 g_WN[T1n * TPn * 16];       // per-bucket {sum aw, (float)count}
__device__ float  g_SA[T1n * TPn];            // sum m*A^2
__device__ float  g_L64[T1n];                 // loss for c == sta

// ---------------------------------------------------------------------------
// K1: val_v[i][j] = <e1_i/|e1_i|, e2_j/|e2_j|>.
//   Grid (16,16); 256 threads (8 warps). Block = 8 i-rows x 32 j-cols.
//   Stage both tiles ONCE into smem, normalized at store time:
//     s_e1[8][256] row-major  -> broadcast LDS.128 in the loop
//     s_e2t[256][32] k-major  -> conflict-free per-lane scalar LDS
//   Inner loop is pure LDS + FMA; one output per thread.
// ---------------------------------------------------------------------------
__global__ __launch_bounds__(256) void k_val(const float* __restrict__ e1,
                                             const float* __restrict__ e2) {
    int i0 = blockIdx.x * 8;     // 16 i-tiles
    int j0 = blockIdx.y * 32;    // 16 j-tiles
    int tid = threadIdx.x;       // 256
    int lane = tid & 31;

    __shared__ float s_e1[8][Dn];      // 8 KB, row-major normalized
    __shared__ float s_e2t[Dn][32];    // 32 KB, k-major normalized

    // ---- e1 tile: warp w = row w; each lane 2 consecutive float4 (coalesced)
    {
        int row = tid >> 5;
        const float4* rp = (const float4*)(e1 + (i0 + row) * Dn);
        float4 v0 = rp[lane * 2];
        float4 v1 = rp[lane * 2 + 1];
        float ss = v0.x*v0.x + v0.y*v0.y + v0.z*v0.z + v0.w*v0.w
                 + v1.x*v1.x + v1.y*v1.y + v1.z*v1.z + v1.w*v1.w;
        for (int o = 16; o; o >>= 1) ss += __shfl_xor_sync(0xffffffffu, ss, o);
        float inv = rsqrtf(ss);
        float4* dst = (float4*)&s_e1[row][lane * 8];
        dst[0] = make_float4(v0.x * inv, v0.y * inv, v0.z * inv, v0.w * inv);
        dst[1] = make_float4(v1.x * inv, v1.y * inv, v1.z * inv, v1.w * inv);
    }
    // ---- e2 tile: 32 rows, 8 threads/row, 8 float4 each (coalesced)
    {
        int r2 = tid >> 3, c8 = tid & 7;
        const float4* rp = (const float4*)(e2 + (j0 + r2) * Dn);
        float4 w[8];
        float ss = 0.f;
        #pragma unroll
        for (int u = 0; u < 8; u++) {
            w[u] = rp[c8 + 8 * u];
            ss = fmaf(w[u].x, w[u].x, ss); ss = fmaf(w[u].y, w[u].y, ss);
            ss = fmaf(w[u].z, w[u].z, ss); ss = fmaf(w[u].w, w[u].w, ss);
        }
        ss += __shfl_xor_sync(0xffffffffu, ss, 1, 8);
        ss += __shfl_xor_sync(0xffffffffu, ss, 2, 8);
        ss += __shfl_xor_sync(0xffffffffu, ss, 4, 8);
        float inv = rsqrtf(ss);
        #pragma unroll
        for (int u = 0; u < 8; u++) {
            int k = (c8 + 8 * u) * 4;
            s_e2t[k + 0][r2] = w[u].x * inv;
            s_e2t[k + 1][r2] = w[u].y * inv;
            s_e2t[k + 2][r2] = w[u].z * inv;
            s_e2t[k + 3][r2] = w[u].w * inv;
        }
    }
    __syncthreads();

    // ---- main loop: thread = (il = tid>>5, jl = tid&31); one output
    int il = tid >> 5;
    int jl = tid & 31;
    float acc0 = 0.f, acc1 = 0.f;
    #pragma unroll 4
    for (int k = 0; k < Dn; k += 4) {
        float4 a = *(const float4*)&s_e1[il][k];   // broadcast LDS.128
        acc0 = fmaf(a.x, s_e2t[k + 0][jl], acc0);
        acc1 = fmaf(a.y, s_e2t[k + 1][jl], acc1);
        acc0 = fmaf(a.z, s_e2t[k + 2][jl], acc0);
        acc1 = fmaf(a.w, s_e2t[k + 3][jl], acc1);
    }
    g_val[(i0 + il) * T2n + j0 + jl] = acc0 + acc1;
}

// ---------------------------------------------------------------------------
// K2: build. Grid 128 (block per i); 512 threads (16 warps).  (unchanged)
// ---------------------------------------------------------------------------
__global__ __launch_bounds__(512) void k_build(const int* __restrict__ sta,
                                               const int* __restrict__ pos,
                                               const unsigned* __restrict__ mask) {
    int i = blockIdx.x;
    int tid = threadIdx.x;
    int lane = tid & 31, w = tid >> 5;
    unsigned lt = (1u << lane) - 1u;

    __shared__ uint2 s_all[TPn][T2n];     // 32 KB
    __shared__ int   s_cm[TPn][16][16];   // [t][warp][bucket] counts -> offsets
    __shared__ int   s_bs[TPn][17];
    __shared__ int   s_st[TPn];
    __shared__ float s_red[16][9];

    if (tid < TPn) s_st[tid] = sta[i * TPn + tid];
    #pragma unroll
    for (int u = 0; u < 4; u++) ((int*)s_cm)[tid + 512 * u] = 0;
    __syncthreads();

    int j = tid;
    int4 p0 = ((const int4*)pos)[j * 2];
    int4 p1 = ((const int4*)pos)[j * 2 + 1];
    int pv[TPn] = {p0.x, p0.y, p0.z, p0.w, p1.x, p1.y, p1.z, p1.w};
    bool m = (mask[i * T2n + j] != 0u);
    float val = g_val[i * T2n + j];

    float dis[TPn];
    int   ab[TPn];
    float dsum = 0.f;
    #pragma unroll
    for (int tt = 0; tt < TPn; tt++) {
        int stt = s_st[tt];
        int a = stt < 0 ? -stt : stt;
        int b = pv[tt] < 0 ? -pv[tt] : pv[tt];
        ab[tt] = b;
        float sg = ((stt ^ pv[tt]) < 0) ? -1.0f : 1.0f;
        int v = (a ^ b) + 1;
        int p; asm("bfind.u32 %0, %1;" : "=r"(p) : "r"(v));
        float d = sg * (float)(15 - p) * (1.0f / 16.0f);
        dis[tt] = d;
        dsum += d;
    }

    {
        float red9[9];
        float B = dsum * 0.125f - val;
        red9[8] = m ? B * B : 0.0f;
        #pragma unroll
        for (int tt = 0; tt < TPn; tt++) {
            float A = (dsum - dis[tt]) * 0.125f - val;
            red9[tt] = m ? A * A : 0.0f;
        }
        #pragma unroll
        for (int o = 16; o; o >>= 1) {
            #pragma unroll
            for (int x = 0; x < 9; x++)
                red9[x] += __shfl_down_sync(0xffffffffu, red9[x], o);
        }
        if (lane == 0) {
            #pragma unroll
            for (int x = 0; x < 9; x++) s_red[w][x] = red9[x];
        }
    }

    unsigned ball = __ballot_sync(0xffffffffu, m);
    int rank[TPn];
    #pragma unroll
    for (int tt = 0; tt < TPn; tt++) {
        int b = ab[tt] >> 12;
        unsigned same = __match_any_sync(0xffffffffu, b) & ball;
        rank[tt] = __popc(same & lt);
        if (m && rank[tt] == 0) s_cm[tt][w][b] = __popc(same);
    }
    __syncthreads();

    if (w < TPn) {
        int t = w, b = lane & 15;
        int tot = 0;
        #pragma unroll
        for (int ww = 0; ww < 16; ww++) tot += s_cm[t][ww][b];
        int run = tot;
        #pragma unroll
        for (int o = 1; o < 16; o <<= 1) {
            int n = __shfl_up_sync(0xffffffffu, run, o, 16);
            if ((lane & 15) >= o) run += n;
        }
        if (lane < 16) {
            int excl = run - tot;
            s_bs[t][b] = excl;
            if (b == 15) s_bs[t][16] = run;
            int acc = excl;
            #pragma unroll
            for (int ww = 0; ww < 16; ww++) {
                int c = s_cm[t][ww][b]; s_cm[t][ww][b] = acc; acc += c;
            }
        }
    }
    if (tid >= 288 && tid < 297) {
        int x = tid - 288;
        float s = 0.f;
        #pragma unroll
        for (int ww = 0; ww < 16; ww++) s += s_red[ww][x];
        if (x < 8) g_SA[i * TPn + x] = s;
        else       g_L64[i] = s;
    }
    __syncthreads();

    if (m) {
        #pragma unroll
        for (int tt = 0; tt < TPn; tt++) {
            float A = (dsum - dis[tt]) * 0.125f - val;
            unsigned awb = __float_as_uint(A * (1.0f / 128.0f)) ^
                           ((unsigned)pv[tt] & 0x80000000u);
            int slot = s_cm[tt][w][ab[tt] >> 12] + rank[tt];
            s_all[tt][slot] = make_uint2(awb, (unsigned)ab[tt]);
        }
    }
    __syncthreads();

    {
        int unit = tid >> 2, q4 = tid & 3;
        int t = unit >> 4, b = unit & 15;
        int lo = s_bs[t][b], hi = s_bs[t][b + 1];
        float ws = 0.f;
        for (int k = lo + q4; k < hi; k += 4) ws += __uint_as_float(s_all[t][k].x);
        ws += __shfl_down_sync(0xffffffffu, ws, 2, 4);
        ws += __shfl_down_sync(0xffffffffu, ws, 1, 4);
        if (q4 == 0)
            g_WN[(i * TPn + t) * 16 + b] = make_float2(ws, (float)(hi - lo));
    }
    int cnt = s_bs[0][16];
    #pragma unroll
    for (int tt = 0; tt < TPn; tt++) {
        if (tid < cnt)
            g_pack[(i * TPn + tt) * T2n + tid] = s_all[tt][tid];
    }
    if (tid < TPn * 17) {
        int t = tid / 17, x = tid % 17;
        g_bs[(i * TPn + t) * 17 + x] = s_bs[t][x];
    }
}

// ---------------------------------------------------------------------------
// K3: loss. Grid (i,t) = (128,8); 256 threads; 4 threads/candidate. (unchanged)
// ---------------------------------------------------------------------------
__device__ __forceinline__ int make_cand(int c, int stav, const int* rm, int i, int t) {
    int h = c >> 2, k = c & 3;
    int r = rm[((i * Hn + h) * Kn + k) * TPn + t];
    return (stav ^ (1 << h)) ^ (r & ((1 << h) - 1));
}

__global__ __launch_bounds__(256, 6) void k_loss(const int* __restrict__ sta,
                                                 const int* __restrict__ rmask,
                                                 float* __restrict__ out) {
    int i = blockIdx.x, t = blockIdx.y;
    int tid = threadIdx.x;

    __shared__ uint2    s_pk[T2n];       // 4 KB
    __shared__ unsigned s_bm[2048];      // 8 KB presence bitmap over ap
    __shared__ int      s_bs[17];
    __shared__ float2   s_WN[16];

    int base = (i * TPn + t);
    if (tid < 17) s_bs[tid] = g_bs[base * 17 + tid];
    else if (tid >= 32 && tid < 48) s_WN[tid - 32] = g_WN[base * 16 + tid - 32];
    #pragma unroll
    for (int u = 0; u < 8; u++) s_bm[tid + 256 * u] = 0u;
    int cnt = __ldg(&g_bs[base * 17 + 16]);
    __syncthreads();

    const uint2* gp = g_pack + base * T2n;
    for (int idx = tid; idx < cnt; idx += 256) {
        uint2 e = gp[idx];
        s_pk[idx] = e;
        atomicOr(&s_bm[e.y >> 5], 1u << (e.y & 31));
    }
    __syncthreads();

    int c  = tid >> 2;                  // 0..63
    int q4 = tid & 3;
    int stav = sta[i * TPn + t];
    int cand = make_cand(c, stav, rmask, i, t);
    unsigned ac = (unsigned)(cand < 0 ? -cand : cand);
    int acH = (int)(ac >> 12);          // 0..16

    float S2 = 0.f, Sq = 0.f;

    #pragma unroll
    for (int u = 0; u < 4; u++) {
        int b = q4 * 4 + u;
        if (b != acH) {
            int xh = acH ^ b;
            int mb; asm("bfind.u32 %0, %1;" : "=r"(mb) : "r"(xh));
            float f = 8388611.0f - __int_as_float(mb | 0x4B000000);   // 3 - mb
            float2 wn = s_WN[b];
            S2 = fmaf(wn.x, f, S2);
            Sq = fmaf(wn.y, f * f, Sq);
        }
    }

    if (acH < 16) {
        int hi = s_bs[acH + 1];
        for (int k = s_bs[acH] + q4; k < hi; k += 4) {
            uint2 e = s_pk[k];
            unsigned v = (ac ^ e.y) + 1u;
            int qq; asm("bfind.u32 %0, %1;" : "=r"(qq) : "r"(v));
            float f = 8388623.0f - __int_as_float(qq | 0x4B000000);   // 15 - qq
            S2 = fmaf(__uint_as_float(e.x), f, S2);
            Sq = fmaf(f, f, Sq);
        }
    }

    #pragma unroll
    for (int pp = 0; pp < 2; pp++) {
        int kk = (pp == 0) ? (13 + q4) : 17;
        if (pp == 1 && q4 != 0) break;
        unsigned rv = ac ^ ((1u << kk) - 1u);
        if (rv <= 65535u) {
            if (s_bm[rv >> 5] & (1u << (rv & 31))) {
                int bb = (int)(rv >> 12);
                int lo = s_bs[bb], hi = s_bs[bb + 1];
                float dq = (float)(2 * kk - 31);
                for (int k = lo; k < hi; k++) {
                    uint2 e = s_pk[k];
                    if (e.y == rv) { S2 -= __uint_as_float(e.x); Sq += dq; }
                }
            }
        }
    }

    S2 += __shfl_down_sync(0xffffffffu, S2, 2, 4);
    S2 += __shfl_down_sync(0xffffffffu, S2, 1, 4);
    Sq += __shfl_down_sync(0xffffffffu, Sq, 2, 4);
    Sq += __shfl_down_sync(0xffffffffu, Sq, 1, 4);

    if (q4 == 0) {
        float SA = g_SA[base];
        float bse = SA + Sq * (1.0f / 16384.0f);
        float sc  = cand < 0 ? -1.0f : 1.0f;
        float tw  = 2.0f * sc * S2;
        float lp  = bse + tw;
        out[(i * Cn + c) * TPn + t] = lp;
        out[(i * Cn + 65 + c) * TPn + t] = (cand == 0) ? lp : (bse - tw);
    }
    if (tid == 0)
        out[(i * Cn + 64) * TPn + t] = g_L64[i];
}

// ---------------------------------------------------------------------------
extern "C" void kernel_launch(void* const* d_in, const int* in_sizes, int n_in,
                              void* d_out, int out_size) {
    const float*    emb1 = (const float*)d_in[0];
    const float*    emb2 = (const float*)d_in[1];
    const int*      sta  = (const int*)d_in[2];
    const int*      pos  = (const int*)d_in[3];
    const unsigned* mask = (const unsigned*)d_in[4];
    const int*      rm   = (const int*)d_in[5];
    float*          out  = (float*)d_out;

    k_val<<<dim3(16, 16), 256>>>(emb1, emb2);
    k_build<<<T1n, 512>>>(sta, pos, mask);
    k_loss<<<dim3(T1n, TPn), 256>>>(sta, rm, out);
}

// round 15
// speedup vs baseline: 1.1115x; 1.1115x over previous
#include <cuda_runtime.h>
#include <cuda_bf16.h>
#include <cstdint>

// ---- problem constants ----
#define T1n 128
#define T2n 512
#define TPn 8
#define Hn  16
#define Kn  4
#define Cn  129   // 2*K*H+1
#define Dn  256

// ---- device scratch ----
__device__ float g_val[T1n * T2n];

// ---- dynamic smem layout for k_mega ----
#define OFF_ALL  0                      // uint2 s_all[8][512]      32768
#define OFF_BM   32768                  // unsigned s_bm[8][2048]   65536
#define OFF_CM   98304                  // int s_cm[8][16][16]       8192
#define OFF_BS   106496                 // int s_bs[8][17]            544
#define OFF_WN   107040                 // float2 s_wn[8][16]        1024
#define OFF_RED  108064                 // float s_red[16][9]         576
#define OFF_ST   108640                 // int s_st[8]                 32
#define OFF_SA   108672                 // float s_SA[8]               32
#define OFF_L64  108704                 // float s_L64                  4
#define SMEM_MEGA 108736

// ---------------------------------------------------------------------------
// K1: val_v[i][j] = <e1_i/|e1_i|, e2_j/|e2_j|>.   (round-14 exact)
//   Grid (16,16); 256 threads. Block = 8 i-rows x 32 j-cols; tiles staged
//   once into smem normalized; pure-LDS inner loop; 1 output/thread.
// ---------------------------------------------------------------------------
__global__ __launch_bounds__(256) void k_val(const float* __restrict__ e1,
                                             const float* __restrict__ e2) {
    int i0 = blockIdx.x * 8;
    int j0 = blockIdx.y * 32;
    int tid = threadIdx.x;
    int lane = tid & 31;

    __shared__ float s_e1[8][Dn];      // 8 KB, row-major normalized
    __shared__ float s_e2t[Dn][32];    // 32 KB, k-major normalized

    {
        int row = tid >> 5;
        const float4* rp = (const float4*)(e1 + (i0 + row) * Dn);
        float4 v0 = rp[lane * 2];
        float4 v1 = rp[lane * 2 + 1];
        float ss = v0.x*v0.x + v0.y*v0.y + v0.z*v0.z + v0.w*v0.w
                 + v1.x*v1.x + v1.y*v1.y + v1.z*v1.z + v1.w*v1.w;
        for (int o = 16; o; o >>= 1) ss += __shfl_xor_sync(0xffffffffu, ss, o);
        float inv = rsqrtf(ss);
        float4* dst = (float4*)&s_e1[row][lane * 8];
        dst[0] = make_float4(v0.x * inv, v0.y * inv, v0.z * inv, v0.w * inv);
        dst[1] = make_float4(v1.x * inv, v1.y * inv, v1.z * inv, v1.w * inv);
    }
    {
        int r2 = tid >> 3, c8 = tid & 7;
        const float4* rp = (const float4*)(e2 + (j0 + r2) * Dn);
        float4 w[8];
        float ss = 0.f;
        #pragma unroll
        for (int u = 0; u < 8; u++) {
            w[u] = rp[c8 + 8 * u];
            ss = fmaf(w[u].x, w[u].x, ss); ss = fmaf(w[u].y, w[u].y, ss);
            ss = fmaf(w[u].z, w[u].z, ss); ss = fmaf(w[u].w, w[u].w, ss);
        }
        ss += __shfl_xor_sync(0xffffffffu, ss, 1, 8);
        ss += __shfl_xor_sync(0xffffffffu, ss, 2, 8);
        ss += __shfl_xor_sync(0xffffffffu, ss, 4, 8);
        float inv = rsqrtf(ss);
        #pragma unroll
        for (int u = 0; u < 8; u++) {
            int k = (c8 + 8 * u) * 4;
            s_e2t[k + 0][r2] = w[u].x * inv;
            s_e2t[k + 1][r2] = w[u].y * inv;
            s_e2t[k + 2][r2] = w[u].z * inv;
            s_e2t[k + 3][r2] = w[u].w * inv;
        }
    }
    __syncthreads();

    int il = tid >> 5;
    int jl = tid & 31;
    float acc0 = 0.f, acc1 = 0.f;
    #pragma unroll 4
    for (int k = 0; k < Dn; k += 4) {
        float4 a = *(const float4*)&s_e1[il][k];
        acc0 = fmaf(a.x, s_e2t[k + 0][jl], acc0);
        acc1 = fmaf(a.y, s_e2t[k + 1][jl], acc1);
        acc0 = fmaf(a.z, s_e2t[k + 2][jl], acc0);
        acc1 = fmaf(a.w, s_e2t[k + 3][jl], acc1);
    }
    g_val[(i0 + il) * T2n + j0 + jl] = acc0 + acc1;
}

// ---------------------------------------------------------------------------
// K2: fused build + loss. Grid 128 (block per i); 512 threads; ~106 KB smem.
//   Phase 1 (j = tid): distance scan, SA_t/L64, counting sort into per-t
//     bucket lists (16 buckets by ap>>12) in smem, per-t presence bitmaps,
//     per-bucket {W,N}. NOTHING goes to gmem.
//   Phase 2 (t = tid>>6, c = tid&63; one candidate per thread):
//     16 bucket aggregates + serial exact scan of matching bucket +
//     ripple fixups (kk in [13,17]) via bitmap probes.
//   Mirrors (65..128): loss± = SA + Sq/16384 ± 2*sc*S2.
// ---------------------------------------------------------------------------
__device__ __forceinline__ int make_cand(int c, int stav, const int* rm, int i, int t) {
    int h = c >> 2, k = c & 3;
    int r = rm[((i * Hn + h) * Kn + k) * TPn + t];
    return (stav ^ (1 << h)) ^ (r & ((1 << h) - 1));
}

__global__ __launch_bounds__(512) void k_mega(const int* __restrict__ sta,
                                              const int* __restrict__ pos,
                                              const unsigned* __restrict__ mask,
                                              const int* __restrict__ rmask,
                                              float* __restrict__ out) {
    extern __shared__ unsigned char smem_raw[];
    uint2    (*s_all)[T2n]   = (uint2(*)[T2n])(smem_raw + OFF_ALL);
    unsigned* s_bm           = (unsigned*)(smem_raw + OFF_BM);     // [8][2048]
    int      (*s_cm)[16][16] = (int(*)[16][16])(smem_raw + OFF_CM);
    int      (*s_bs)[17]     = (int(*)[17])(smem_raw + OFF_BS);
    float2   (*s_wn)[16]     = (float2(*)[16])(smem_raw + OFF_WN);
    float    (*s_red)[9]     = (float(*)[9])(smem_raw + OFF_RED);
    int*      s_st           = (int*)(smem_raw + OFF_ST);
    float*    s_SA           = (float*)(smem_raw + OFF_SA);
    float*    s_L64          = (float*)(smem_raw + OFF_L64);

    int i = blockIdx.x;
    int tid = threadIdx.x;
    int lane = tid & 31, w = tid >> 5;
    unsigned lt = (1u << lane) - 1u;

    if (tid < TPn) s_st[tid] = sta[i * TPn + tid];
    // zero count matrix (2048 ints) + bitmaps (16384 words)
    #pragma unroll
    for (int u = 0; u < 4; u++) ((int*)s_cm)[tid + 512 * u] = 0;
    #pragma unroll
    for (int u = 0; u < 32; u++) s_bm[tid + 512 * u] = 0u;
    __syncthreads();

    // ---- phase 1: distance scan ----
    int j = tid;
    int4 p0 = ((const int4*)pos)[j * 2];
    int4 p1 = ((const int4*)pos)[j * 2 + 1];
    int pv[TPn] = {p0.x, p0.y, p0.z, p0.w, p1.x, p1.y, p1.z, p1.w};
    bool m = (mask[i * T2n + j] != 0u);
    float val = g_val[i * T2n + j];

    float dis[TPn];
    int   ab[TPn];
    float dsum = 0.f;
    #pragma unroll
    for (int tt = 0; tt < TPn; tt++) {
        int stt = s_st[tt];
        int a = stt < 0 ? -stt : stt;
        int b = pv[tt] < 0 ? -pv[tt] : pv[tt];
        ab[tt] = b;
        float sg = ((stt ^ pv[tt]) < 0) ? -1.0f : 1.0f;
        int v = (a ^ b) + 1;
        int p; asm("bfind.u32 %0, %1;" : "=r"(p) : "r"(v));
        float d = sg * (float)(15 - p) * (1.0f / 16.0f);
        dis[tt] = d;
        dsum += d;
    }

    // SA_t and L64 reductions
    {
        float red9[9];
        float B = dsum * 0.125f - val;
        red9[8] = m ? B * B : 0.0f;
        #pragma unroll
        for (int tt = 0; tt < TPn; tt++) {
            float A = (dsum - dis[tt]) * 0.125f - val;
            red9[tt] = m ? A * A : 0.0f;
        }
        #pragma unroll
        for (int o = 16; o; o >>= 1) {
            #pragma unroll
            for (int x = 0; x < 9; x++)
                red9[x] += __shfl_down_sync(0xffffffffu, red9[x], o);
        }
        if (lane == 0) {
            #pragma unroll
            for (int x = 0; x < 9; x++) s_red[w][x] = red9[x];
        }
    }

    // per-(t,warp,bucket) counts
    unsigned ball = __ballot_sync(0xffffffffu, m);
    int rank[TPn];
    #pragma unroll
    for (int tt = 0; tt < TPn; tt++) {
        int b = ab[tt] >> 12;
        unsigned same = __match_any_sync(0xffffffffu, b) & ball;
        rank[tt] = __popc(same & lt);
        if (m && rank[tt] == 0) s_cm[tt][w][b] = __popc(same);
    }
    __syncthreads();

    // warps 0..7 scan their t (all 32 lanes run width-16 shfl; writes lane<16)
    if (w < TPn) {
        int t = w, b = lane & 15;
        int tot = 0;
        #pragma unroll
        for (int ww = 0; ww < 16; ww++) tot += s_cm[t][ww][b];
        int run = tot;
        #pragma unroll
        for (int o = 1; o < 16; o <<= 1) {
            int n = __shfl_up_sync(0xffffffffu, run, o, 16);
            if ((lane & 15) >= o) run += n;
        }
        if (lane < 16) {
            int excl = run - tot;
            s_bs[t][b] = excl;
            if (b == 15) s_bs[t][16] = run;
            int acc = excl;
            #pragma unroll
            for (int ww = 0; ww < 16; ww++) {
                int c = s_cm[t][ww][b]; s_cm[t][ww][b] = acc; acc += c;
            }
        }
    }
    // SA/L64 finalize (threads 288..296) -> smem
    if (tid >= 288 && tid < 297) {
        int x = tid - 288;
        float s = 0.f;
        #pragma unroll
        for (int ww = 0; ww < 16; ww++) s += s_red[ww][x];
        if (x < 8) s_SA[x] = s;
        else       s_L64[0] = s;
    }
    __syncthreads();

    // scatter all 8 t into smem + set presence bitmaps
    if (m) {
        #pragma unroll
        for (int tt = 0; tt < TPn; tt++) {
            float A = (dsum - dis[tt]) * 0.125f - val;
            unsigned awb = __float_as_uint(A * (1.0f / 128.0f)) ^
                           ((unsigned)pv[tt] & 0x80000000u);
            int slot = s_cm[tt][w][ab[tt] >> 12] + rank[tt];
            s_all[tt][slot] = make_uint2(awb, (unsigned)ab[tt]);
            atomicOr(&s_bm[tt * 2048 + (ab[tt] >> 5)], 1u << (ab[tt] & 31));
        }
    }
    __syncthreads();

    // W/N per (t,b): 128 units x 4 threads
    {
        int unit = tid >> 2, q4 = tid & 3;
        int t = unit >> 4, b = unit & 15;
        int lo = s_bs[t][b], hi = s_bs[t][b + 1];
        float ws = 0.f;
        for (int k = lo + q4; k < hi; k += 4) ws += __uint_as_float(s_all[t][k].x);
        ws += __shfl_down_sync(0xffffffffu, ws, 2, 4);
        ws += __shfl_down_sync(0xffffffffu, ws, 1, 4);
        if (q4 == 0)
            s_wn[t][b] = make_float2(ws, (float)(hi - lo));
    }
    __syncthreads();

    // ---- phase 2: one candidate per thread ----
    int t = tid >> 6;                   // 0..7
    int c = tid & 63;                   // 0..63
    int stav = s_st[t];
    int cand = make_cand(c, stav, rmask, i, t);
    unsigned ac = (unsigned)(cand < 0 ? -cand : cand);
    int acH = (int)(ac >> 12);          // 0..16

    const uint2*    pk  = s_all[t];
    const int*      bst = s_bs[t];
    const float2*   wnt = s_wn[t];
    const unsigned* bmt = s_bm + t * 2048;

    float S2 = 0.f, Sq = 0.f;

    // (a) bucket aggregates
    #pragma unroll
    for (int b = 0; b < 16; b++) {
        if (b != acH) {
            int xh = acH ^ b;
            int mb; asm("bfind.u32 %0, %1;" : "=r"(mb) : "r"(xh));
            float f = 8388611.0f - __int_as_float(mb | 0x4B000000);   // 3 - mb
            float2 wn = wnt[b];
            S2 = fmaf(wn.x, f, S2);
            Sq = fmaf(wn.y, f * f, Sq);
        }
    }

    // (b) exact scan of matching bucket (serial)
    if (acH < 16) {
        int hi = bst[acH + 1];
        for (int k = bst[acH]; k < hi; k++) {
            uint2 e = pk[k];
            unsigned v = (ac ^ e.y) + 1u;
            int qq; asm("bfind.u32 %0, %1;" : "=r"(qq) : "r"(v));
            float f = 8388623.0f - __int_as_float(qq | 0x4B000000);   // 15 - qq
            S2 = fmaf(__uint_as_float(e.x), f, S2);
            Sq = fmaf(f, f, Sq);
        }
    }

    // (c) ripple fixups: kk in [13,17], bitmap-probed
    #pragma unroll
    for (int kk = 13; kk <= 17; kk++) {
        unsigned rv = ac ^ ((1u << kk) - 1u);
        if (rv <= 65535u) {
            if ((bmt[rv >> 5] >> (rv & 31)) & 1u) {
                int bb = (int)(rv >> 12);
                int lo = bst[bb], hi = bst[bb + 1];
                float dq = (float)(2 * kk - 31);
                for (int k = lo; k < hi; k++) {
                    uint2 e = pk[k];
                    if (e.y == rv) { S2 -= __uint_as_float(e.x); Sq += dq; }
                }
            }
        }
    }

    {
        float SA  = s_SA[t];
        float bse = SA + Sq * (1.0f / 16384.0f);
        float sc  = cand < 0 ? -1.0f : 1.0f;
        float tw  = 2.0f * sc * S2;
        float lp  = bse + tw;
        out[(i * Cn + c) * TPn + t] = lp;
        out[(i * Cn + 65 + c) * TPn + t] = (cand == 0) ? lp : (bse - tw);
        if (c == 0)
            out[(i * Cn + 64) * TPn + t] = s_L64[0];
    }
}

// ---------------------------------------------------------------------------
extern "C" void kernel_launch(void* const* d_in, const int* in_sizes, int n_in,
                              void* d_out, int out_size) {
    const float*    emb1 = (const float*)d_in[0];
    const float*    emb2 = (const float*)d_in[1];
    const int*      sta  = (const int*)d_in[2];
    const int*      pos  = (const int*)d_in[3];
    const unsigned* mask = (const unsigned*)d_in[4];
    const int*      rm   = (const int*)d_in[5];
    float*          out  = (float*)d_out;

    static bool attr_done = false;
    if (!attr_done) {
        cudaFuncSetAttribute(k_mega, cudaFuncAttributeMaxDynamicSharedMemorySize,
                             SMEM_MEGA);
        attr_done = true;
    }

    k_val<<<dim3(16, 16), 256>>>(emb1, emb2);
    k_mega<<<T1n, 512, SMEM_MEGA>>>(sta, pos, mask, rm, out);
}